// round 1
// baseline (speedup 1.0000x reference)
#include <cuda_runtime.h>
#include <math.h>

// ---------------------------------------------------------------------------
// TrLaplacianDP: out = embs + noise, where noise[0:300] are the first 300
// accepted samples of a truncated-Laplacian rejection scan over (sgn, u).
// ---------------------------------------------------------------------------

#define EMBS_DIM 300
#define T_A 1024

// Scratch noise buffer (device global — no allocations allowed).
// 304 floats so it is cleanly float4-addressable (75 usable float4 + pad).
__device__ __align__(16) float g_noise[304];

// ---------------------------------------------------------------------------
// Kernel A: single-block ordered rejection scan.
// Computes r = -SCALE * sign(sgn) * log(u); accepts |r| <= A; writes the
// k-th accepted value (k < 300) to g_noise[k]. Early-exits once 300 found.
// ---------------------------------------------------------------------------
__global__ void __launch_bounds__(T_A) noise_kernel(const float* __restrict__ sgn,
                                                    const float* __restrict__ u,
                                                    int n) {
    // Constants computed in double precision at runtime (immune to
    // --use_fast_math rewrites of single-precision transcendentals).
    const double SCALE_D = 2.0 * 0.005 * sqrt(300.0) / 1.0;
    const float  SCALE_F = (float)SCALE_D;
    const float  A_F     = (float)(-SCALE_D * log(1.0 - 2.0 * 1.0 / sqrt(300.0)));

    __shared__ int s_count;        // accepted so far (before current chunk)
    __shared__ int s_warp[32];     // per-warp accept counts
    __shared__ int s_warp_off[33]; // exclusive offsets; [32] = running total

    const int tid  = threadIdx.x;
    const int lane = tid & 31;
    const int wid  = tid >> 5;

    // Zero the noise buffer (covers the "fewer than 300 accepted" case and
    // the 4 pad floats).
    if (tid < 304) g_noise[tid] = 0.0f;
    if (tid == 0) s_count = 0;
    __syncthreads();

    for (int base = 0; base < n; base += T_A) {
        const int idx = base + tid;
        float r = 0.0f;
        bool mask = false;
        if (idx < n) {
            const float sv = sgn[idx];
            const float s  = (sv > 0.0f) ? 1.0f : ((sv < 0.0f) ? -1.0f : 0.0f);
            // double-precision log, rounded to float: matches fp32 reference
            // to ~1 ulp regardless of compiler fast-math settings.
            const float lg = (float)log((double)u[idx]);
            r = (-SCALE_F * s) * lg;
            mask = (r >= -A_F) && (r <= A_F);
        }

        // Block-wide ordered exclusive prefix of `mask`.
        const unsigned b = __ballot_sync(0xffffffffu, mask);
        const int wprefix = __popc(b & ((1u << lane) - 1u));
        if (lane == 0) s_warp[wid] = __popc(b);
        __syncthreads();
        if (tid == 0) {
            int acc = s_count;
            #pragma unroll
            for (int w = 0; w < 32; ++w) { s_warp_off[w] = acc; acc += s_warp[w]; }
            s_warp_off[32] = acc;
        }
        __syncthreads();

        if (mask) {
            const int pos = s_warp_off[wid] + wprefix;
            if (pos < EMBS_DIM) g_noise[pos] = r;
        }
        if (tid == 0) s_count = s_warp_off[32];
        __syncthreads();

        if (s_warp_off[32] >= EMBS_DIM) break;   // uniform across the block
    }
}

// ---------------------------------------------------------------------------
// Kernel B: out = embs + broadcast(noise). Pure HBM-bound float4 streaming.
// Column tracked incrementally: float4 index v covers elements 4v..4v+3,
// and since 300 = 4*75, the noise float4 index is v % 75.
// ---------------------------------------------------------------------------
__global__ void __launch_bounds__(256) add_kernel(const float* __restrict__ embs,
                                                  float* __restrict__ out,
                                                  int n4, int n) {
    __shared__ float4 s_noise[75];
    if (threadIdx.x < 75)
        s_noise[threadIdx.x] = reinterpret_cast<const float4*>(g_noise)[threadIdx.x];
    __syncthreads();

    const float4* __restrict__ in4  = reinterpret_cast<const float4*>(embs);
    float4* __restrict__       out4 = reinterpret_cast<float4*>(out);

    const int stride = gridDim.x * blockDim.x;
    int v = blockIdx.x * blockDim.x + threadIdx.x;
    int c  = v % 75;              // one real modulo, then incremental update
    const int sm = stride % 75;

    #pragma unroll 4
    for (; v < n4; v += stride) {
        float4 e  = in4[v];
        const float4 nz = s_noise[c];
        e.x += nz.x; e.y += nz.y; e.z += nz.z; e.w += nz.w;
        out4[v] = e;
        c += sm; if (c >= 75) c -= 75;
    }

    // Scalar tail (n not divisible by 4 — defensive; unused for this shape).
    const int tail_start = n4 * 4;
    for (int i = tail_start + blockIdx.x * blockDim.x + threadIdx.x; i < n;
         i += stride) {
        out[i] = embs[i] + g_noise[i % EMBS_DIM];
    }
}

// ---------------------------------------------------------------------------
extern "C" void kernel_launch(void* const* d_in, const int* in_sizes, int n_in,
                              void* d_out, int out_size) {
    const float* embs = (const float*)d_in[0];
    const float* sgn  = (const float*)d_in[1];
    const float* u    = (const float*)d_in[2];
    float* out        = (float*)d_out;

    const int nsamp = in_sizes[1];
    noise_kernel<<<1, T_A>>>(sgn, u, nsamp);

    const int n  = out_size;
    const int n4 = n / 4;
    const int iters_per_thread = 8;
    int grid = (n4 + 256 * iters_per_thread - 1) / (256 * iters_per_thread);
    if (grid < 1) grid = 1;
    add_kernel<<<grid, 256>>>(embs, out, n4, n);
}

// round 2
// speedup vs baseline: 1.3897x; 1.3897x over previous
#include <cuda_runtime.h>
#include <math.h>

// ---------------------------------------------------------------------------
// TrLaplacianDP: out = embs + noise, where noise[0:300] are the first 300
// accepted samples of a truncated-Laplacian rejection scan over (sgn, u).
//
// R2: the per-sample mask/r computation (double-precision log, FP64-heavy)
// is parallelized across 64 blocks for the first NCAP samples; a single
// small block then ranks the mask bits and gathers the first 300 values.
// ---------------------------------------------------------------------------

#define EMBS_DIM 300
#define NCAP     16384           // samples pre-scanned in parallel
#define NWORDS   (NCAP / 32)     // 512 ballot words

// Device scratch (no allocations allowed).
__device__ __align__(16) float    g_noise[304];   // 75 float4 + pad
__device__ __align__(16) float    g_r[NCAP];
__device__                unsigned g_maskw[NWORDS];

__device__ __forceinline__ void compute_r_mask(float sv, float uv,
                                               float SCALE_F, float A_F,
                                               float& r, bool& m) {
    const float s  = (sv > 0.0f) ? 1.0f : ((sv < 0.0f) ? -1.0f : 0.0f);
    // log in double precision: immune to fast-math rewrites; matches the
    // fp32 reference to ~1 ulp at the acceptance boundary.
    const float lg = (float)log((double)uv);
    r = (-SCALE_F * s) * lg;
    m = (r >= -A_F) && (r <= A_F);
}

// ---------------------------------------------------------------------------
// Kernel A1: parallel mask/r precompute for samples [0, NCAP).
// ---------------------------------------------------------------------------
__global__ void __launch_bounds__(256) mask_kernel(const float* __restrict__ sgn,
                                                   const float* __restrict__ u,
                                                   int n) {
    const double SCALE_D = 2.0 * 0.005 * sqrt(300.0) / 1.0;
    const float  SCALE_F = (float)SCALE_D;
    const float  A_F     = (float)(-SCALE_D * log(1.0 - 2.0 * 1.0 / sqrt(300.0)));

    const int i = blockIdx.x * blockDim.x + threadIdx.x;   // 0..NCAP-1
    float r = 0.0f;
    bool  m = false;
    if (i < n) compute_r_mask(sgn[i], u[i], SCALE_F, A_F, r, m);

    g_r[i] = r;
    const unsigned b = __ballot_sync(0xffffffffu, m);
    if ((threadIdx.x & 31) == 0) g_maskw[i >> 5] = b;
}

// ---------------------------------------------------------------------------
// Kernel A2 (1 block x 512): rank the mask bits, gather first 300 accepted r
// into g_noise. Serial fallback past NCAP only if the cap was insufficient.
// ---------------------------------------------------------------------------
__global__ void __launch_bounds__(512) gather_kernel(const float* __restrict__ sgn,
                                                     const float* __restrict__ u,
                                                     int n) {
    const double SCALE_D = 2.0 * 0.005 * sqrt(300.0) / 1.0;
    const float  SCALE_F = (float)SCALE_D;
    const float  A_F     = (float)(-SCALE_D * log(1.0 - 2.0 * 1.0 / sqrt(300.0)));

    const int t    = threadIdx.x;        // 0..511, one ballot word each
    const int lane = t & 31;
    const int wid  = t >> 5;             // 16 warps

    __shared__ int s_wsum[16];
    __shared__ int s_total;

    if (t < 304) g_noise[t] = 0.0f;

    const unsigned word = g_maskw[t];
    const int cnt = __popc(word);

    // Inclusive warp scan of per-word counts.
    int incl = cnt;
    #pragma unroll
    for (int o = 1; o < 32; o <<= 1) {
        const int v = __shfl_up_sync(0xffffffffu, incl, o);
        if (lane >= o) incl += v;
    }
    if (lane == 31) s_wsum[wid] = incl;
    __syncthreads();

    if (wid == 0 && lane < 16) {
        const int v = s_wsum[lane];
        int iv = v;
        #pragma unroll
        for (int o = 1; o < 16; o <<= 1) {
            const int x = __shfl_up_sync(0x0000ffffu, iv, o);
            if (lane >= o) iv += x;
        }
        s_wsum[lane] = iv - v;                 // exclusive warp offsets
        if (lane == 15) s_total = iv;          // grand total over NCAP
    }
    __syncthreads();

    const int base = s_wsum[wid] + (incl - cnt);   // exclusive prefix of word t

    if (base < EMBS_DIM && word) {
        unsigned w2 = word;
        int pos = base;
        while (w2 && pos < EMBS_DIM) {
            const int b = __ffs(w2) - 1;
            g_noise[pos] = g_r[t * 32 + b];
            w2 &= (w2 - 1);
            ++pos;
        }
    }

    // ----- Fallback: cap insufficient (astronomically rare; correctness) ----
    int total = s_total;
    if (total >= EMBS_DIM || n <= NCAP) return;

    __shared__ int s_warpcnt[16];
    __shared__ int s_woff[17];
    for (int bs = NCAP; bs < n; bs += 512) {
        const int idx = bs + t;
        float r = 0.0f;
        bool  m = false;
        if (idx < n) compute_r_mask(sgn[idx], u[idx], SCALE_F, A_F, r, m);

        const unsigned b  = __ballot_sync(0xffffffffu, m);
        const int wprefix = __popc(b & ((1u << lane) - 1u));
        if (lane == 0) s_warpcnt[wid] = __popc(b);
        __syncthreads();
        if (t == 0) {
            int acc = total;
            #pragma unroll
            for (int w = 0; w < 16; ++w) { s_woff[w] = acc; acc += s_warpcnt[w]; }
            s_woff[16] = acc;
        }
        __syncthreads();
        if (m) {
            const int pos = s_woff[wid] + wprefix;
            if (pos < EMBS_DIM) g_noise[pos] = r;
        }
        total = s_woff[16];
        __syncthreads();
        if (total >= EMBS_DIM) return;
    }
}

// ---------------------------------------------------------------------------
// Kernel B: out = embs + broadcast(noise). Pure HBM-bound float4 streaming.
// Launcher guarantees (gridDim.x * blockDim.x) % 75 == 0, so each thread's
// noise float4 index (v % 75) is INVARIANT across grid-stride iterations.
// ---------------------------------------------------------------------------
__global__ void __launch_bounds__(256) add_kernel(const float* __restrict__ embs,
                                                  float* __restrict__ out,
                                                  int n4, int n) {
    __shared__ float4 s_noise[75];
    if (threadIdx.x < 75)
        s_noise[threadIdx.x] = reinterpret_cast<const float4*>(g_noise)[threadIdx.x];
    __syncthreads();

    const float4* __restrict__ in4  = reinterpret_cast<const float4*>(embs);
    float4* __restrict__       out4 = reinterpret_cast<float4*>(out);

    const int stride = gridDim.x * blockDim.x;       // multiple of 75
    const int v0     = blockIdx.x * blockDim.x + threadIdx.x;
    const float4 nz  = s_noise[v0 % 75];

    // Grid-stride, unrolled x8: 8 independent predicated LDG.128 per pass.
    for (int v = v0; v < n4; v += 8 * stride) {
        #pragma unroll
        for (int k = 0; k < 8; ++k) {
            const int vi = v + k * stride;
            if (vi < n4) {
                float4 e = __ldcs(&in4[vi]);
                e.x += nz.x; e.y += nz.y; e.z += nz.z; e.w += nz.w;
                __stcs(&out4[vi], e);
            }
        }
    }

    // Scalar tail (n not divisible by 4 — defensive; unused for this shape).
    const int tail_start = n4 * 4;
    for (int i = tail_start + v0; i < n; i += stride)
        out[i] = embs[i] + g_noise[i % EMBS_DIM];
}

// ---------------------------------------------------------------------------
extern "C" void kernel_launch(void* const* d_in, const int* in_sizes, int n_in,
                              void* d_out, int out_size) {
    const float* embs = (const float*)d_in[0];
    const float* sgn  = (const float*)d_in[1];
    const float* u    = (const float*)d_in[2];
    float* out        = (float*)d_out;

    const int nsamp = in_sizes[1];
    mask_kernel<<<NCAP / 256, 256>>>(sgn, u, nsamp);
    gather_kernel<<<1, 512>>>(sgn, u, nsamp);

    const int n  = out_size;
    const int n4 = n / 4;
    // grid: ~8 float4 per thread, rounded UP to a multiple of 75 so that
    // (grid*256) % 75 == 0  (gcd(256,75)=1 -> grid must be a multiple of 75).
    int grid = (n4 + 256 * 8 - 1) / (256 * 8);
    grid = ((grid + 74) / 75) * 75;
    if (grid < 75) grid = 75;
    add_kernel<<<grid, 256>>>(embs, out, n4, n);
}